// round 1
// baseline (speedup 1.0000x reference)
#include <cuda_runtime.h>
#include <cstdint>
#include <cstddef>

// Problem constants
#define B_   256
#define D_   512
#define K_   128000
#define N_   100000
#define TOPK_  5
#define TOPKP_ 10

// ---------------- device scratch (no allocations allowed) ----------------
__device__ float g_St [32768000];   // [B, K] dist_t = 2 - 2*<t, queue_eff>
__device__ float g_Stp[32768000];   // [B, K] dist_tp
__device__ float g_tnorm[B_ * D_];
__device__ float g_qnorm[B_ * D_];
__device__ float g_ct   [B_ * D_];  // ct_prime rows (gathered pool rows)
__device__ int   g_eq[N_];          // effective pool_qindex after update
__device__ int   g_idxp [B_ * TOPKP_];
__device__ int   g_unidx[B_ * TOPK_];
__device__ float g_pb_un[B_], g_pb_con[B_], g_pb_pur[B_];

#define FLTMAX 3.402823466e+38f

// ---------------- prep kernels ----------------
__global__ void k_eq_copy(const int* __restrict__ pool_qindex) {
    int i = blockIdx.x * blockDim.x + threadIdx.x;
    if (i < N_) g_eq[i] = pool_qindex[i];
}

__global__ void k_eq_set(const int* __restrict__ indices,
                         const int* __restrict__ pool_qindex) {
    int b = threadIdx.x;              // 256 threads
    int n = indices[b];
    g_eq[n] = 1 - pool_qindex[n];     // duplicate writes store same value
}

// one block per row b; 256 threads; normalize query and current_target
__global__ void k_norm(const float* __restrict__ query,
                       const float* __restrict__ ctgt) {
    int b = blockIdx.x, t = threadIdx.x;
    __shared__ float red[256];

    // query
    float x0 = query[b * D_ + t], x1 = query[b * D_ + t + 256];
    red[t] = x0 * x0 + x1 * x1;
    __syncthreads();
    for (int s = 128; s > 0; s >>= 1) {
        if (t < s) red[t] += red[t + s];
        __syncthreads();
    }
    float nq = sqrtf(red[0]);
    __syncthreads();
    g_qnorm[b * D_ + t]       = x0 / nq;
    g_qnorm[b * D_ + t + 256] = x1 / nq;

    // current_target
    float y0 = ctgt[b * D_ + t], y1 = ctgt[b * D_ + t + 256];
    red[t] = y0 * y0 + y1 * y1;
    __syncthreads();
    for (int s = 128; s > 0; s >>= 1) {
        if (t < s) red[t] += red[t + s];
        __syncthreads();
    }
    float nt = sqrtf(red[0]);
    __syncthreads();
    g_tnorm[b * D_ + t]       = y0 / nt;
    g_tnorm[b * D_ + t + 256] = y1 / nt;
}

// gather ct_prime rows: ct[b] = pool[eq[indices[b]], indices[b]]
__global__ void k_gather_ct(const float* __restrict__ pool,
                            const int* __restrict__ indices) {
    int b = blockIdx.x, t = threadIdx.x;  // 128 threads, float4
    int n = indices[b];
    const float4* src = (const float4*)(pool + ((size_t)g_eq[n] * N_ + (size_t)n) * D_);
    ((float4*)(g_ct + b * D_))[t] = src[t];
}

// ---------------- score GEMMs ----------------
// MODE 0: A = g_tnorm, Brow(k) = (k<256 ? t_norm[k] : queue[k])      -> g_St
// MODE 1: A = g_ct,    Brow(k) = pool[eq[ik], ik], ik per updated iq -> g_Stp
template <int MODE>
__global__ __launch_bounds__(256)
void k_gemm(const float* __restrict__ queue,
            const float* __restrict__ pool,
            const int* __restrict__ indices,
            const int* __restrict__ index_queue,
            float* __restrict__ out) {
    constexpr int BM = 128, BN = 128, BK = 16;
    __shared__ float As[BK][BM + 4];
    __shared__ float Bs[BK][BN + 4];
    __shared__ const float* rowp[BN];

    const float* A = (MODE == 0) ? g_tnorm : g_ct;
    const int bm = blockIdx.y * BM;
    const int bn = blockIdx.x * BN;
    const int tid = threadIdx.x;

    if (tid < BN) {
        int kg = bn + tid;
        const float* p;
        if (MODE == 0) {
            p = (kg < B_) ? (g_tnorm + kg * D_) : (queue + (size_t)kg * D_);
        } else {
            int ik = (kg < B_) ? indices[kg] : index_queue[kg];
            p = pool + ((size_t)g_eq[ik] * N_ + (size_t)ik) * D_;
        }
        rowp[tid] = p;
    }
    __syncthreads();

    float acc[8][8];
#pragma unroll
    for (int i = 0; i < 8; i++)
#pragma unroll
        for (int j = 0; j < 8; j++) acc[i][j] = 0.f;

    const int tx = tid & 15;    // N direction
    const int ty = tid >> 4;    // M direction
    const int lrow  = tid >> 2; // 0..63
    const int lcol4 = tid & 3;  // 0..3

    for (int kk = 0; kk < D_; kk += BK) {
#pragma unroll
        for (int it = 0; it < 2; it++) {
            int r = lrow + it * 64;
            float4 v = *(const float4*)(A + (size_t)(bm + r) * D_ + kk + lcol4 * 4);
            As[lcol4 * 4 + 0][r] = v.x;
            As[lcol4 * 4 + 1][r] = v.y;
            As[lcol4 * 4 + 2][r] = v.z;
            As[lcol4 * 4 + 3][r] = v.w;
        }
#pragma unroll
        for (int it = 0; it < 2; it++) {
            int r = lrow + it * 64;
            float4 v = *(const float4*)(rowp[r] + kk + lcol4 * 4);
            Bs[lcol4 * 4 + 0][r] = v.x;
            Bs[lcol4 * 4 + 1][r] = v.y;
            Bs[lcol4 * 4 + 2][r] = v.z;
            Bs[lcol4 * 4 + 3][r] = v.w;
        }
        __syncthreads();
#pragma unroll
        for (int c = 0; c < BK; c++) {
            float a[8], bb[8];
#pragma unroll
            for (int i = 0; i < 8; i++) a[i]  = As[c][ty * 8 + i];
#pragma unroll
            for (int j = 0; j < 8; j++) bb[j] = Bs[c][tx * 8 + j];
#pragma unroll
            for (int i = 0; i < 8; i++)
#pragma unroll
                for (int j = 0; j < 8; j++) acc[i][j] += a[i] * bb[j];
        }
        __syncthreads();
    }

    // epilogue: store dist = 2 - 2*ip  (matches reference quantization for ties)
#pragma unroll
    for (int i = 0; i < 8; i++) {
        size_t base = (size_t)(bm + ty * 8 + i) * K_ + bn + tx * 8;
        float4 v0, v1;
        v0.x = 2.f - 2.f * acc[i][0]; v0.y = 2.f - 2.f * acc[i][1];
        v0.z = 2.f - 2.f * acc[i][2]; v0.w = 2.f - 2.f * acc[i][3];
        v1.x = 2.f - 2.f * acc[i][4]; v1.y = 2.f - 2.f * acc[i][5];
        v1.z = 2.f - 2.f * acc[i][6]; v1.w = 2.f - 2.f * acc[i][7];
        *(float4*)(out + base)     = v0;
        *(float4*)(out + base + 4) = v1;
    }
}

// ---------------- top-k (smallest value, ties -> smaller index) ----------------
template <int T>
__global__ void k_topk(const float* __restrict__ S, int* __restrict__ outIdx) {
    int b = blockIdx.x;
    const float* row = S + (size_t)b * K_;
    float v[T];
    int   id[T];
#pragma unroll
    for (int i = 0; i < T; i++) { v[i] = FLTMAX; id[i] = 0x7fffffff; }

    for (int k = threadIdx.x; k < K_; k += 256) {
        float x = row[k];
        if (x < v[T - 1] || (x == v[T - 1] && k < id[T - 1])) {
            int pos = T - 1;
            while (pos > 0 && (x < v[pos - 1] || (x == v[pos - 1] && k < id[pos - 1]))) {
                v[pos] = v[pos - 1]; id[pos] = id[pos - 1]; pos--;
            }
            v[pos] = x; id[pos] = k;
        }
    }

    __shared__ float sv[256];
    __shared__ int   si[256];
    int hp = 0;
    for (int r = 0; r < T; r++) {
        sv[threadIdx.x] = (hp < T) ? v[hp]  : FLTMAX;
        si[threadIdx.x] = (hp < T) ? id[hp] : 0x7fffffff;
        __syncthreads();
        for (int s = 128; s > 0; s >>= 1) {
            if (threadIdx.x < s) {
                float ov = sv[threadIdx.x + s]; int oi = si[threadIdx.x + s];
                if (ov < sv[threadIdx.x] ||
                    (ov == sv[threadIdx.x] && oi < si[threadIdx.x])) {
                    sv[threadIdx.x] = ov; si[threadIdx.x] = oi;
                }
            }
            __syncthreads();
        }
        int wi = si[0];
        if (threadIdx.x == 0) outIdx[b * T + r] = wi;
        if (hp < T && id[hp] == wi) hp++;
        __syncthreads();
    }
}

// ---------------- final per-row evaluation ----------------
__global__ void k_final(const float* __restrict__ queue,
                        const int* __restrict__ labels_bank,
                        const int* __restrict__ labels) {
    int b = blockIdx.x, t = threadIdx.x;
    __shared__ int conIdx[TOPK_];
    __shared__ float red[256];

    if (t == 0) {
        // con_idx = 5 smallest dist_t among the 10 constrained positions
        float pv[TOPKP_]; int pi[TOPKP_];
        for (int j = 0; j < TOPKP_; j++) {
            int k = g_idxp[b * TOPKP_ + j];
            pi[j] = k;
            pv[j] = g_St[(size_t)b * K_ + k];
        }
        for (int r = 0; r < TOPK_; r++) {
            int best = r;
            for (int j = r + 1; j < TOPKP_; j++)
                if (pv[j] < pv[best] || (pv[j] == pv[best] && pi[j] < pi[best])) best = j;
            float tv = pv[r]; pv[r] = pv[best]; pv[best] = tv;
            int ti = pi[r]; pi[r] = pi[best]; pi[best] = ti;
            conIdx[r] = pi[r];
        }
    }
    __syncthreads();

    __shared__ float s_un, s_con;
    __shared__ int   s_match;
    if (t == 0) { s_un = 0.f; s_con = 0.f; s_match = 0; }
    __syncthreads();

    const float* qr = g_qnorm + b * D_;
    for (int j = 0; j < 2 * TOPK_; j++) {
        int k = (j < TOPK_) ? g_unidx[b * TOPK_ + j] : conIdx[j - TOPK_];
        const float* rowk = (k < B_) ? (g_tnorm + k * D_) : (queue + (size_t)k * D_);
        float p = qr[t] * rowk[t] + qr[t + 256] * rowk[t + 256];
        red[t] = p;
        __syncthreads();
        for (int s = 128; s > 0; s >>= 1) {
            if (t < s) red[t] += red[t + s];
            __syncthreads();
        }
        if (t == 0) {
            float d = 2.f - 2.f * red[0];
            if (j < TOPK_) {
                s_un += d;
                int lab = (k < B_) ? labels[k] : labels_bank[k];
                if (lab == labels[b]) s_match++;
            } else {
                s_con += d;
            }
        }
        __syncthreads();
    }
    if (t == 0) {
        g_pb_un[b]  = s_un  / (float)TOPK_;
        g_pb_con[b] = s_con / (float)TOPK_;
        g_pb_pur[b] = (float)s_match / (float)TOPK_;
    }
}

__global__ void k_finalize(float* __restrict__ out, int out_size) {
    float su = 0.f, sc = 0.f, sp = 0.f;
    for (int b = 0; b < B_; b++) {
        su += g_pb_un[b];
        sc += g_pb_con[b];
        sp += g_pb_pur[b];
    }
    float loss   = (sc / (float)B_ + su / (float)B_) * 0.5f;
    float purity = sp / (float)B_;
    out[0] = loss;
    if (out_size > 1) out[1] = purity;
}

// ---------------- launch ----------------
extern "C" void kernel_launch(void* const* d_in, const int* in_sizes, int n_in,
                              void* d_out, int out_size) {
    const float* query       = (const float*)d_in[0];
    const float* ctgt        = (const float*)d_in[1];
    const float* queue       = (const float*)d_in[2];
    const float* pool        = (const float*)d_in[3];
    const int*   labels_bank = (const int*)d_in[4];
    const int*   index_queue = (const int*)d_in[5];
    const int*   pool_qindex = (const int*)d_in[6];
    const int*   labels      = (const int*)d_in[7];
    const int*   indices     = (const int*)d_in[8];

    float* St_ptr;  cudaGetSymbolAddress((void**)&St_ptr,  g_St);
    float* Stp_ptr; cudaGetSymbolAddress((void**)&Stp_ptr, g_Stp);
    int* idxp_ptr;  cudaGetSymbolAddress((void**)&idxp_ptr,  g_idxp);
    int* unidx_ptr; cudaGetSymbolAddress((void**)&unidx_ptr, g_unidx);

    // prep
    k_eq_copy<<<(N_ + 255) / 256, 256>>>(pool_qindex);
    k_eq_set<<<1, 256>>>(indices, pool_qindex);
    k_norm<<<B_, 256>>>(query, ctgt);
    k_gather_ct<<<B_, 128>>>(pool, indices);

    // score GEMMs
    dim3 gg(K_ / 128, B_ / 128);
    k_gemm<0><<<gg, 256>>>(queue, pool, indices, index_queue, St_ptr);
    k_gemm<1><<<gg, 256>>>(queue, pool, indices, index_queue, Stp_ptr);

    // top-k selections
    k_topk<TOPKP_><<<B_, 256>>>(Stp_ptr, idxp_ptr);
    k_topk<TOPK_><<<B_, 256>>>(St_ptr,  unidx_ptr);

    // final evaluation + reduction
    k_final<<<B_, 256>>>(queue, labels_bank, labels);
    k_finalize<<<1, 1>>>((float*)d_out, out_size);
}